// round 6
// baseline (speedup 1.0000x reference)
#include <cuda_runtime.h>

// SSIM loss, (32,1,512,512) fp32. Single fused kernel, f32x2-packed FIR.
// R5: no input staging (h-pass reads global directly, aligned LDG.128 fast
//     path), single-phase h over 64-wide tile, single-phase v with 8-row
//     register blocking, 4 barriers/block, fused last-block mean.

#define IMG   512
#define TW    64
#define TH    32
#define SR    42          // TH + 10 h-buffer rows
#define HPIT  66          // hxy pitch (f2)
#define PPIT  68          // hp  pitch (f32)
#define GX    8
#define GY    16
#define GZ    32
#define NBLK  (GX * GY * GZ)   // 4096

__device__ float        g_partials[NBLK];
__device__ unsigned int g_count;     // zero-init; self-resets

// normalized 1D Gaussian, K=11, sigma=1.5
#define W0 0.00102838f
#define W1 0.00759876f
#define W2 0.03600077f
#define W3 0.10936060f
#define W4 0.21300553f
#define W5 0.26601172f

#define FMA2(d, a, b, c) \
    asm("fma.rn.f32x2 %0, %1, %2, %3;" : "=l"(d) : "l"(a), "l"(b), "l"(c))
#define UNPK(lo, hi, v) \
    asm("mov.b64 {%0, %1}, %2;" : "=f"(lo), "=f"(hi) : "l"(v))
#define PK(v, lo, hi) \
    asm("mov.b64 %0, {%1, %2};" : "=l"(v) : "f"(lo), "f"(hi))

__device__ __forceinline__ unsigned long long pk2(float w) {
    unsigned long long r;
    asm("mov.b64 %0, {%1, %1};" : "=l"(r) : "f"(w));
    return r;
}

__global__ __launch_bounds__(256, 5)
void ssim_fused_kernel(const float* __restrict__ X, const float* __restrict__ Y,
                       float* __restrict__ out)
{
    __shared__ unsigned long long hxy[SR][HPIT];   // h-conv packed (x,y) 21.7KB
    __shared__ float              hp [SR][PPIT];   // h-conv (x*y)        11.2KB
    __shared__ float              wsum[8];
    __shared__ int                s_last;

    const float WGs[11] = {W0, W1, W2, W3, W4, W5, W4, W3, W2, W1, W0};
    const unsigned long long p0 = pk2(W0), p1 = pk2(W1), p2 = pk2(W2),
                             p3 = pk2(W3), p4 = pk2(W4), p5 = pk2(W5);
    const unsigned long long WP[11] = {p0,p1,p2,p3,p4,p5,p4,p3,p2,p1,p0};

    const int tid  = threadIdx.x;
    const int img  = blockIdx.z;
    const int row0 = blockIdx.y * TH - 5;
    const int col0 = blockIdx.x * TW - 5;

    const float* __restrict__ Xi = X + (size_t)img * IMG * IMG;
    const float* __restrict__ Yi = Y + (size_t)img * IMG * IMG;

    const bool colsafe = (blockIdx.x >= 1) && (blockIdx.x <= 6);

    // ------- horizontal streaming FIR from GLOBAL: 336 items x 8 outputs -------
    #pragma unroll 1
    for (int i = tid; i < SR * 8; i += 256) {
        const int r  = i >> 3;
        const int o  = i & 7;
        const int c0 = o * 8;
        const int gr = row0 + r;

        unsigned long long acc2[8];
        float accp[8];
        #pragma unroll
        for (int j = 0; j < 8; j++) { acc2[j] = 0ull; accp[j] = 0.0f; }

        if ((unsigned)gr < (unsigned)IMG) {
            if (colsafe) {
                // window cols W..W+17, W = col0+c0 == 3 (mod 4); A = W-3 aligned
                const float* bx = Xi + gr * IMG + (col0 + c0 - 3);
                const float* by = Yi + gr * IMG + (col0 + c0 - 3);
                float xw[24], yw[24];
                #pragma unroll
                for (int q = 0; q < 6; q++) {
                    float4 a = __ldg((const float4*)(bx + 4 * q));
                    float4 b = __ldg((const float4*)(by + 4 * q));
                    xw[4*q+0] = a.x; xw[4*q+1] = a.y; xw[4*q+2] = a.z; xw[4*q+3] = a.w;
                    yw[4*q+0] = b.x; yw[4*q+1] = b.y; yw[4*q+2] = b.z; yw[4*q+3] = b.w;
                }
                #pragma unroll
                for (int m = 0; m < 18; m++) {
                    float xv = xw[m + 3], yv = yw[m + 3];
                    unsigned long long v;
                    PK(v, xv, yv);
                    float pm = xv * yv;
                    #pragma unroll
                    for (int j = 0; j < 8; j++) {
                        const int k = m - j;
                        if (k >= 0 && k <= 10) {
                            FMA2(acc2[j], v, WP[k], acc2[j]);
                            accp[j] = fmaf(WGs[k], pm, accp[j]);
                        }
                    }
                }
            } else {
                // boundary columns: guarded scalar loads
                const int gw = col0 + c0;
                #pragma unroll
                for (int m = 0; m < 18; m++) {
                    const int gc = gw + m;
                    float xv = 0.0f, yv = 0.0f;
                    if ((unsigned)gc < (unsigned)IMG) {
                        xv = __ldg(&Xi[gr * IMG + gc]);
                        yv = __ldg(&Yi[gr * IMG + gc]);
                    }
                    unsigned long long v;
                    PK(v, xv, yv);
                    float pm = xv * yv;
                    #pragma unroll
                    for (int j = 0; j < 8; j++) {
                        const int k = m - j;
                        if (k >= 0 && k <= 10) {
                            FMA2(acc2[j], v, WP[k], acc2[j]);
                            accp[j] = fmaf(WGs[k], pm, accp[j]);
                        }
                    }
                }
            }
        }
        // always store (zeros for OOR rows)
        #pragma unroll
        for (int j = 0; j < 8; j += 2)
            *(ulonglong2*)&hxy[r][c0 + j] = make_ulonglong2(acc2[j], acc2[j + 1]);
        *(float4*)&hp[r][c0]     = make_float4(accp[0], accp[1], accp[2], accp[3]);
        *(float4*)&hp[r][c0 + 4] = make_float4(accp[4], accp[5], accp[6], accp[7]);
    }
    __syncthreads();

    // ------- vertical streaming FIR + SSIM: col(64) x rowgroup(4), 8 rows each -------
    const float C1 = 0.0001f, C2 = 0.0009f;
    float lsum = 0.0f;
    {
        const int c   = tid & 63;
        const int r0v = (tid >> 6) * 8;

        unsigned long long acc2[8];
        float accp[8];
        #pragma unroll
        for (int j = 0; j < 8; j++) { acc2[j] = 0ull; accp[j] = 0.0f; }

        #pragma unroll
        for (int m = 0; m < 18; m++) {
            unsigned long long v = hxy[r0v + m][c];
            float pm = hp[r0v + m][c];
            #pragma unroll
            for (int j = 0; j < 8; j++) {
                const int k = m - j;
                if (k >= 0 && k <= 10) {
                    FMA2(acc2[j], v, WP[k], acc2[j]);
                    accp[j] = fmaf(WGs[k], pm, accp[j]);
                }
            }
        }
        #pragma unroll
        for (int j = 0; j < 8; j++) {
            float mu1, mu2;
            UNPK(mu1, mu2, acc2[j]);
            float m12 = mu1 * mu2;
            float sig = accp[j] - m12;
            float sq  = mu1 * mu1 + mu2 * mu2;
            float num = (2.0f * m12 + C1) * (2.0f * sig + C2);
            float den = (sq + C1) * (sq + C2);
            lsum += __fdividef(num, den);
        }
    }

    // ---------------- block reduction ----------------
    #pragma unroll
    for (int off = 16; off > 0; off >>= 1)
        lsum += __shfl_xor_sync(0xFFFFFFFFu, lsum, off);
    if ((tid & 31) == 0) wsum[tid >> 5] = lsum;
    __syncthreads();
    if (tid == 0) {
        float v = 0.0f;
        #pragma unroll
        for (int w = 0; w < 8; w++) v += wsum[w];
        int bid = blockIdx.x + GX * (blockIdx.y + GY * blockIdx.z);
        g_partials[bid] = v;
        __threadfence();
        unsigned int ticket = atomicAdd(&g_count, 1u);
        s_last = (ticket == NBLK - 1);
    }
    __syncthreads();

    // ---------------- last block: final reduction ----------------
    if (s_last) {
        float s = 0.0f;
        #pragma unroll 4
        for (int i = tid; i < NBLK; i += 256)
            s += *((volatile float*)&g_partials[i]);
        #pragma unroll
        for (int off = 16; off > 0; off >>= 1)
            s += __shfl_xor_sync(0xFFFFFFFFu, s, off);
        __syncthreads();
        if ((tid & 31) == 0) wsum[tid >> 5] = s;
        __syncthreads();
        if (tid == 0) {
            float v = 0.0f;
            #pragma unroll
            for (int w = 0; w < 8; w++) v += wsum[w];
            out[0]  = v * (1.0f / 8388608.0f);
            g_count = 0;
        }
    }
}

extern "C" void kernel_launch(void* const* d_in, const int* in_sizes, int n_in,
                              void* d_out, int out_size)
{
    (void)in_sizes; (void)n_in; (void)out_size;
    const float* X_gt   = (const float*)d_in[0];
    const float* X_pred = (const float*)d_in[1];
    float* out = (float*)d_out;

    dim3 grid(GX, GY, GZ);
    ssim_fused_kernel<<<grid, 256>>>(X_gt, X_pred, out);
}

// round 7
// speedup vs baseline: 1.3850x; 1.3850x over previous
#include <cuda_runtime.h>

// SSIM loss, (32,1,512,512) fp32. Single fused kernel, f32x2-packed FIR.
// R6: VERTICAL-FIRST separable conv.
//  phase 1: v-conv straight from global (thread-per-column streaming, coalesced,
//           zero overlap-amplification), results staged as 3 scalar smem planes
//  phase 2: h-conv from smem (conflict-free: pitch 75 = 11 mod 32) + SSIM
//  2 barriers/block, balanced 256/256 items, fused last-block mean.

#define IMG   512
#define TW    64
#define TH    32
#define VC    74          // v-conv cols staged (TW + 10)
#define PIT   75          // smem pitch (f32): 75 % 32 = 11, gcd(11,32)=1
#define GX    8
#define GY    16
#define GZ    32
#define NBLK  (GX * GY * GZ)   // 4096

__device__ float        g_partials[NBLK];
__device__ unsigned int g_count;     // zero-init; self-resets

// normalized 1D Gaussian, K=11, sigma=1.5
#define W0 0.00102838f
#define W1 0.00759876f
#define W2 0.03600077f
#define W3 0.10936060f
#define W4 0.21300553f
#define W5 0.26601172f

#define FMA2(d, a, b, c) \
    asm("fma.rn.f32x2 %0, %1, %2, %3;" : "=l"(d) : "l"(a), "l"(b), "l"(c))
#define UNPK(lo, hi, v) \
    asm("mov.b64 {%0, %1}, %2;" : "=f"(lo), "=f"(hi) : "l"(v))
#define PK(v, lo, hi) \
    asm("mov.b64 %0, {%1, %2};" : "=l"(v) : "f"(lo), "f"(hi))

__device__ __forceinline__ unsigned long long pk2(float w) {
    unsigned long long r;
    asm("mov.b64 %0, {%1, %1};" : "=l"(r) : "f"(w));
    return r;
}

__global__ __launch_bounds__(256, 5)
void ssim_fused_kernel(const float* __restrict__ X, const float* __restrict__ Y,
                       float* __restrict__ out)
{
    __shared__ float vx[TH][PIT];    // v-conv of x    9.4KB
    __shared__ float vy[TH][PIT];    // v-conv of y    9.4KB
    __shared__ float vp[TH][PIT];    // v-conv of x*y  9.4KB
    __shared__ float wsum[8];
    __shared__ int   s_last;

    const float WGs[11] = {W0, W1, W2, W3, W4, W5, W4, W3, W2, W1, W0};
    const unsigned long long p0 = pk2(W0), p1 = pk2(W1), p2 = pk2(W2),
                             p3 = pk2(W3), p4 = pk2(W4), p5 = pk2(W5);
    const unsigned long long WP[11] = {p0,p1,p2,p3,p4,p5,p4,p3,p2,p1,p0};

    const int tid  = threadIdx.x;
    const int img  = blockIdx.z;
    const int row0 = blockIdx.y * TH - 5;
    const int col0 = blockIdx.x * TW - 5;

    const float* __restrict__ Xi = X + (size_t)img * IMG * IMG;
    const float* __restrict__ Yi = Y + (size_t)img * IMG * IMG;

    // rows row0 .. row0+41 all in-range for by = 1..14
    const bool rowsafe = (row0 >= 0) && (row0 + TH + 9 < IMG);

    // ---- phase 1: vertical streaming FIR from GLOBAL: 296 items ----
    // item = (column c of 74, rowgroup g of 4); 8 outputs, reads 18 rows.
    #pragma unroll 1
    for (int i = tid; i < VC * 4; i += 256) {
        const int c  = i % VC;
        const int g  = i / VC;
        const int gc = col0 + c;
        const int rb = row0 + g * 8;

        unsigned long long acc2[8];
        float accp[8];
        #pragma unroll
        for (int j = 0; j < 8; j++) { acc2[j] = 0ull; accp[j] = 0.0f; }

        if ((unsigned)gc < (unsigned)IMG) {
            const float* __restrict__ px = Xi + gc;
            const float* __restrict__ py = Yi + gc;
            if (rowsafe) {
                #pragma unroll
                for (int m = 0; m < 18; m++) {
                    const int off = (rb + m) * IMG;
                    float xv = __ldg(px + off);
                    float yv = __ldg(py + off);
                    unsigned long long v;
                    PK(v, xv, yv);
                    float pm = xv * yv;
                    #pragma unroll
                    for (int j = 0; j < 8; j++) {
                        const int k = m - j;
                        if (k >= 0 && k <= 10) {
                            FMA2(acc2[j], v, WP[k], acc2[j]);
                            accp[j] = fmaf(WGs[k], pm, accp[j]);
                        }
                    }
                }
            } else {
                #pragma unroll
                for (int m = 0; m < 18; m++) {
                    const int gr = rb + m;
                    float xv = 0.0f, yv = 0.0f;
                    if ((unsigned)gr < (unsigned)IMG) {
                        xv = __ldg(px + gr * IMG);
                        yv = __ldg(py + gr * IMG);
                    }
                    unsigned long long v;
                    PK(v, xv, yv);
                    float pm = xv * yv;
                    #pragma unroll
                    for (int j = 0; j < 8; j++) {
                        const int k = m - j;
                        if (k >= 0 && k <= 10) {
                            FMA2(acc2[j], v, WP[k], acc2[j]);
                            accp[j] = fmaf(WGs[k], pm, accp[j]);
                        }
                    }
                }
            }
        }
        #pragma unroll
        for (int j = 0; j < 8; j++) {
            float xo, yo;
            UNPK(xo, yo, acc2[j]);
            const int vr = g * 8 + j;
            vx[vr][c] = xo;
            vy[vr][c] = yo;
            vp[vr][c] = accp[j];
        }
    }
    __syncthreads();

    // ---- phase 2: horizontal FIR from smem + SSIM: 256 items ----
    // item = (row r of 32, colgroup o of 8); 8 outputs, reads 18 cols x 3 ch.
    const float C1 = 0.0001f, C2 = 0.0009f;
    float lsum = 0.0f;
    {
        const int r  = tid & 31;
        const int c0 = (tid >> 5) * 8;

        unsigned long long acc2[8];
        float accp[8];
        #pragma unroll
        for (int j = 0; j < 8; j++) { acc2[j] = 0ull; accp[j] = 0.0f; }

        #pragma unroll
        for (int m = 0; m < 18; m++) {
            float xv = vx[r][c0 + m];
            float yv = vy[r][c0 + m];
            float pm = vp[r][c0 + m];
            unsigned long long v;
            PK(v, xv, yv);
            #pragma unroll
            for (int j = 0; j < 8; j++) {
                const int k = m - j;
                if (k >= 0 && k <= 10) {
                    FMA2(acc2[j], v, WP[k], acc2[j]);
                    accp[j] = fmaf(WGs[k], pm, accp[j]);
                }
            }
        }
        #pragma unroll
        for (int j = 0; j < 8; j++) {
            float mu1, mu2;
            UNPK(mu1, mu2, acc2[j]);
            float m12 = mu1 * mu2;
            float sig = accp[j] - m12;
            float sq  = mu1 * mu1 + mu2 * mu2;
            float num = (2.0f * m12 + C1) * (2.0f * sig + C2);
            float den = (sq + C1) * (sq + C2);
            lsum += __fdividef(num, den);
        }
    }

    // ---------------- block reduction ----------------
    #pragma unroll
    for (int off = 16; off > 0; off >>= 1)
        lsum += __shfl_xor_sync(0xFFFFFFFFu, lsum, off);
    if ((tid & 31) == 0) wsum[tid >> 5] = lsum;
    __syncthreads();
    if (tid == 0) {
        float v = 0.0f;
        #pragma unroll
        for (int w = 0; w < 8; w++) v += wsum[w];
        int bid = blockIdx.x + GX * (blockIdx.y + GY * blockIdx.z);
        g_partials[bid] = v;
        __threadfence();
        unsigned int ticket = atomicAdd(&g_count, 1u);
        s_last = (ticket == NBLK - 1);
    }
    __syncthreads();

    // ---------------- last block: final reduction ----------------
    if (s_last) {
        float s = 0.0f;
        #pragma unroll 4
        for (int i = tid; i < NBLK; i += 256)
            s += *((volatile float*)&g_partials[i]);
        #pragma unroll
        for (int off = 16; off > 0; off >>= 1)
            s += __shfl_xor_sync(0xFFFFFFFFu, s, off);
        __syncthreads();
        if ((tid & 31) == 0) wsum[tid >> 5] = s;
        __syncthreads();
        if (tid == 0) {
            float v = 0.0f;
            #pragma unroll
            for (int w = 0; w < 8; w++) v += wsum[w];
            out[0]  = v * (1.0f / 8388608.0f);
            g_count = 0;
        }
    }
}

extern "C" void kernel_launch(void* const* d_in, const int* in_sizes, int n_in,
                              void* d_out, int out_size)
{
    (void)in_sizes; (void)n_in; (void)out_size;
    const float* X_gt   = (const float*)d_in[0];
    const float* X_pred = (const float*)d_in[1];
    float* out = (float*)d_out;

    dim3 grid(GX, GY, GZ);
    ssim_fused_kernel<<<grid, 256>>>(X_gt, X_pred, out);
}